// round 1
// baseline (speedup 1.0000x reference)
#include <cuda_runtime.h>

#define NN 8192
#define HH 16
#define NHEAD 4
#define SLICES 8
#define TILE 256

// ---------------- device scratch (no allocations allowed) ----------------
__device__ float  g_Hseq[NN * HH];            // LSTM hidden states
__device__ float4 g_Q[NN * NHEAD];            // pre-scaled queries [n][h]
__device__ float4 g_K[NN * NHEAD];
__device__ float4 g_V[NN * NHEAD];
__device__ float  g_Pden[SLICES * NN * NHEAD];   // partial softmax denominators
__device__ float4 g_Pctx[SLICES * NN * NHEAD];   // partial weighted V sums
__device__ float  g_Pblk[32 * 3];                // per-block readout partial sums

// ---------------- kernel 1: serial LSTM, one warp ----------------
// Lane L computes gate rows L and L+32 (i/g for lanes 0-15, f/o for 16-31).
// h (16 values) replicated in every lane's registers via shuffles. No barriers.
__global__ void lstm_kernel(const float* __restrict__ t,
                            const float* __restrict__ W_ih,
                            const float* __restrict__ W_hh,
                            const float* __restrict__ b_ih,
                            const float* __restrict__ b_hh) {
    __shared__ float tsh[NN];
    const int lane = threadIdx.x;
    for (int i = lane; i < NN; i += 32) tsh[i] = t[i];

    const int r1 = lane, r2 = lane + 32;
    float w1[HH], w2[HH];
#pragma unroll
    for (int k = 0; k < HH; k++) {
        w1[k] = W_hh[r1 * HH + k];
        w2[k] = W_hh[r2 * HH + k];
    }
    const float wi1 = W_ih[r1], wi2 = W_ih[r2];
    const float bb1 = b_ih[r1] + b_hh[r1];
    const float bb2 = b_ih[r2] + b_hh[r2];

    float h[HH];
#pragma unroll
    for (int k = 0; k < HH; k++) h[k] = 0.0f;
    float c = 0.0f;
    const bool lo = (lane < 16);
    const int peer = (lane & 15) + 16;

    __syncwarp();

    for (int step = 0; step < NN; step++) {
        const float x = tsh[step];
        // gate pre-activations (two accumulators per row to shorten dep chain)
        float g1a = fmaf(wi1, x, bb1), g1b = 0.0f;
        float g2a = fmaf(wi2, x, bb2), g2b = 0.0f;
#pragma unroll
        for (int k = 0; k < HH; k += 2) {
            g1a = fmaf(w1[k],     h[k],     g1a);
            g1b = fmaf(w1[k + 1], h[k + 1], g1b);
            g2a = fmaf(w2[k],     h[k],     g2a);
            g2b = fmaf(w2[k + 1], h[k + 1], g2b);
        }
        const float g1 = g1a + g1b;
        const float g2 = g2a + g2b;

        // a1 = sigmoid(g1)  (i for lanes 0-15, f for lanes 16-31)
        const float a1 = __fdividef(1.0f, 1.0f + __expf(-g1));
        // a2: tanh(g2) for lanes 0-15 (g-gate), sigmoid(g2) for 16-31 (o-gate)
        // tanh(x) = 2*sigmoid(2x) - 1  -> single exp for both cases
        const float s2 = lo ? (2.0f * g2) : g2;
        const float e2 = __fdividef(1.0f, 1.0f + __expf(-s2));
        const float a2 = lo ? fmaf(2.0f, e2, -1.0f) : e2;

        // lanes 0-15 fetch f, o from lanes 16-31
        const float fg = __shfl_sync(0xffffffffu, a1, peer);
        const float og = __shfl_sync(0xffffffffu, a2, peer);

        c = fmaf(fg, c, a1 * a2);                       // c = f*c + i*g
        const float ec = __fdividef(1.0f, 1.0f + __expf(-2.0f * c));
        const float tc = fmaf(2.0f, ec, -1.0f);         // tanh(c)
        const float hn = og * tc;

        if (lane < 16) g_Hseq[step * HH + lane] = hn;

#pragma unroll
        for (int k = 0; k < HH; k++)
            h[k] = __shfl_sync(0xffffffffu, hn, k);
    }
}

// ---------------- kernel 2: QKV projection ----------------
__global__ void qkv_kernel(const float* __restrict__ in_proj_w,
                           const float* __restrict__ in_proj_b) {
    const int idx = blockIdx.x * blockDim.x + threadIdx.x;
    if (idx >= NN * 48) return;
    const int n = idx / 48;
    const int j = idx % 48;
    const float* hr = g_Hseq + n * HH;
    float acc = in_proj_b[j];
#pragma unroll
    for (int k = 0; k < HH; k++)
        acc = fmaf(__ldg(in_proj_w + j * HH + k), hr[k], acc);

    if (j < 16)       ((float*)g_Q)[n * HH + j]        = acc * 0.5f;  // 1/sqrt(HD)
    else if (j < 32)  ((float*)g_K)[n * HH + (j - 16)] = acc;
    else              ((float*)g_V)[n * HH + (j - 32)] = acc;
}

// ---------------- kernel 3: attention (no max-shift; scores bounded) ------
// Block: 256 threads = 4 heads x 64 queries (warps uniform in head -> all
// shared loads broadcast). Grid: (128 query-blocks, 8 key-slices).
__global__ void attn_kernel() {
    __shared__ float4 Ksh[TILE * NHEAD];
    __shared__ float4 Vsh[TILE * NHEAD];

    const int tid = threadIdx.x;
    const int h   = tid >> 6;
    const int ql  = tid & 63;
    const int q   = blockIdx.x * 64 + ql;
    const int s   = blockIdx.y;

    const float4 qv = g_Q[q * NHEAD + h];
    float den = 0.0f;
    float4 acc = make_float4(0.0f, 0.0f, 0.0f, 0.0f);

    const int kbase0 = s * (NN / SLICES);
    for (int tile = 0; tile < (NN / SLICES) / TILE; tile++) {
        const int kb = kbase0 + tile * TILE;
        __syncthreads();
#pragma unroll
        for (int r = 0; r < 4; r++) {
            Ksh[tid + 256 * r] = g_K[kb * NHEAD + tid + 256 * r];
            Vsh[tid + 256 * r] = g_V[kb * NHEAD + tid + 256 * r];
        }
        __syncthreads();

#pragma unroll 4
        for (int kk = 0; kk < TILE; kk++) {
            const float4 kvv = Ksh[kk * NHEAD + h];
            float sc = qv.x * kvv.x;
            sc = fmaf(qv.y, kvv.y, sc);
            sc = fmaf(qv.z, kvv.z, sc);
            sc = fmaf(qv.w, kvv.w, sc);
            const float p = __expf(sc);
            den += p;
            const float4 vv = Vsh[kk * NHEAD + h];
            acc.x = fmaf(p, vv.x, acc.x);
            acc.y = fmaf(p, vv.y, acc.y);
            acc.z = fmaf(p, vv.z, acc.z);
            acc.w = fmaf(p, vv.w, acc.w);
        }
    }

    const int o = (s * NN + q) * NHEAD + h;
    g_Pden[o] = den;
    g_Pctx[o] = acc;
}

// ---------------- kernel 4: combine + out_proj + residual + LN + readout --
__global__ void finalize_kernel(const float* __restrict__ out_proj_w,
                                const float* __restrict__ out_proj_b,
                                const float* __restrict__ ln_w,
                                const float* __restrict__ ln_b,
                                const float* __restrict__ out_w) {
    const int q = blockIdx.x * 256 + threadIdx.x;

    float ctx[HH];
#pragma unroll
    for (int h = 0; h < NHEAD; h++) {
        float den = 0.0f;
        float4 a = make_float4(0.0f, 0.0f, 0.0f, 0.0f);
#pragma unroll
        for (int s = 0; s < SLICES; s++) {
            const int o = (s * NN + q) * NHEAD + h;
            den += g_Pden[o];
            const float4 p = g_Pctx[o];
            a.x += p.x; a.y += p.y; a.z += p.z; a.w += p.w;
        }
        const float inv = __fdividef(1.0f, den);
        ctx[h * 4 + 0] = a.x * inv;
        ctx[h * 4 + 1] = a.y * inv;
        ctx[h * 4 + 2] = a.z * inv;
        ctx[h * 4 + 3] = a.w * inv;
    }

    // out_proj + residual
    float y[HH];
#pragma unroll
    for (int r = 0; r < HH; r++) {
        float t = out_proj_b[r];
#pragma unroll
        for (int cc = 0; cc < HH; cc++)
            t = fmaf(__ldg(out_proj_w + r * HH + cc), ctx[cc], t);
        y[r] = t + g_Hseq[q * HH + r];
    }

    // LayerNorm over 16
    float mu = 0.0f;
#pragma unroll
    for (int r = 0; r < HH; r++) mu += y[r];
    mu *= (1.0f / HH);
    float var = 0.0f;
#pragma unroll
    for (int r = 0; r < HH; r++) {
        const float d = y[r] - mu;
        var = fmaf(d, d, var);
    }
    var *= (1.0f / HH);
    const float rstd = rsqrtf(var + 1e-5f);

    float z[HH];
#pragma unroll
    for (int r = 0; r < HH; r++)
        z[r] = (y[r] - mu) * rstd * ln_w[r] + ln_b[r];

    // readout (out_b added once at the end in reduce_kernel)
    float raw[3];
#pragma unroll
    for (int j = 0; j < 3; j++) {
        float t = 0.0f;
#pragma unroll
        for (int r = 0; r < HH; r++)
            t = fmaf(__ldg(out_w + j * HH + r), z[r], t);
        raw[j] = t;
    }

    // block reduction: warp shuffle then cross-warp via shared
    __shared__ float wsum[8][3];
    const int lane = threadIdx.x & 31;
    const int wid  = threadIdx.x >> 5;
#pragma unroll
    for (int j = 0; j < 3; j++) {
        float v = raw[j];
#pragma unroll
        for (int off = 16; off > 0; off >>= 1)
            v += __shfl_xor_sync(0xffffffffu, v, off);
        if (lane == 0) wsum[wid][j] = v;
    }
    __syncthreads();
    if (threadIdx.x < 3) {
        float v = 0.0f;
#pragma unroll
        for (int w = 0; w < 8; w++) v += wsum[w][threadIdx.x];
        g_Pblk[blockIdx.x * 3 + threadIdx.x] = v;
    }
}

// ---------------- kernel 5: final reduction ----------------
__global__ void reduce_kernel(const float* __restrict__ out_b, float* out) {
    if (threadIdx.x < 3) {
        float s = 0.0f;
        for (int b = 0; b < 32; b++) s += g_Pblk[b * 3 + threadIdx.x];
        out[threadIdx.x] = s * (1.0f / (float)NN) + out_b[threadIdx.x];
    }
}

// ---------------- launch ----------------
extern "C" void kernel_launch(void* const* d_in, const int* in_sizes, int n_in,
                              void* d_out, int out_size) {
    (void)in_sizes; (void)n_in; (void)out_size;
    const float* t          = (const float*)d_in[0];
    const float* W_ih       = (const float*)d_in[1];
    const float* W_hh       = (const float*)d_in[2];
    const float* b_ih       = (const float*)d_in[3];
    const float* b_hh       = (const float*)d_in[4];
    const float* in_proj_w  = (const float*)d_in[5];
    const float* in_proj_b  = (const float*)d_in[6];
    const float* out_proj_w = (const float*)d_in[7];
    const float* out_proj_b = (const float*)d_in[8];
    const float* ln_w       = (const float*)d_in[9];
    const float* ln_b       = (const float*)d_in[10];
    const float* out_w      = (const float*)d_in[11];
    const float* out_b      = (const float*)d_in[12];
    float* out = (float*)d_out;

    lstm_kernel<<<1, 32>>>(t, W_ih, W_hh, b_ih, b_hh);
    qkv_kernel<<<(NN * 48 + 255) / 256, 256>>>(in_proj_w, in_proj_b);
    dim3 ag(NN / 64, SLICES);
    attn_kernel<<<ag, 256>>>();
    finalize_kernel<<<NN / 256, 256>>>(out_proj_w, out_proj_b, ln_w, ln_b, out_w);
    reduce_kernel<<<1, 32>>>(out_b, out);
}